// round 4
// baseline (speedup 1.0000x reference)
#include <cuda_runtime.h>
#include <math.h>

// Problem constants: B=8, N=4096, C=768, H=8, D=96
constexpr int M_TOK = 8 * 4096;   // 32768 tokens
constexpr int K_IN  = 768;        // C

// ---- device scratch (allocation-free rule: use __device__ globals) ----
__device__ float g_Wr[96 * 768];   // w1 * sum_h W_qkv_rgb[1536 + h*96 + d, :]
__device__ float g_Wd[96 * 768];   // w0 * sum_h W_qkv_depth[768 + h*96 + d, :]
__device__ float g_bg[96];         // combined bias for g
__device__ float g_Wf[768 * 96];   // Wout folded over heads: sum_q W_out[c, q*96+d]
__device__ float g_G[32768 * 96];  // intermediate g[n,d]

// Packed dual-fp32 FMA (sm_103a FFMA2). acc(2 lanes) += a(2 lanes) * b(2 lanes)
#define FMA2(c, a, b) \
    asm("fma.rn.f32x2 %0, %1, %2, %0;" : "+l"(c) : "l"(a), "l"(b))

// ============================================================
// Prep: fold heads into the weights (tiny)
// ============================================================
__global__ void prep_kernel(const float* __restrict__ W1, const float* __restrict__ b1,
                            const float* __restrict__ W2, const float* __restrict__ b2,
                            const float* __restrict__ Wout, const float* __restrict__ aw)
{
    int idx = blockIdx.x * blockDim.x + threadIdx.x;   // 0 .. 73727
    float w0 = 1.0f / (1.0f + expf(-aw[0]));
    float w1 = 1.0f / (1.0f + expf(-aw[1]));

    if (idx < 96 * 768) {
        int d = idx / 768;
        int c = idx - d * 768;
        float sr = 0.0f, sd = 0.0f;
#pragma unroll
        for (int h = 0; h < 8; h++) {
            sr += W1[(size_t)(1536 + h * 96 + d) * 768 + c];
            sd += W2[(size_t)(768  + h * 96 + d) * 768 + c];
        }
        g_Wr[idx] = w1 * sr;
        g_Wd[idx] = w0 * sd;
    }
    if (idx < 768 * 96) {
        int c = idx / 96;
        int d = idx - c * 96;
        float s = 0.0f;
#pragma unroll
        for (int q = 0; q < 8; q++) s += Wout[(size_t)c * 768 + q * 96 + d];
        g_Wf[idx] = s;
    }
    if (idx < 96) {
        float sbr = 0.0f, sbd = 0.0f;
#pragma unroll
        for (int h = 0; h < 8; h++) {
            sbr += b1[1536 + h * 96 + idx];
            sbd += b2[768  + h * 96 + idx];
        }
        g_bg[idx] = w0 * sbd + w1 * sbr;
    }
}

// ============================================================
// GEMM-G:  G[32768, 96] = Xr @ g_Wr^T + Xd @ g_Wd^T + g_bg
// Virtual K = 1536. BM=128, BN=96, BK=16, 256 threads.
// Thread tile 8m x 6n, computed as 8 x 3 f32x2 pairs (FFMA2).
// A is stored DUPLICATED in shared so (a,a) lane pairs come
// straight from LDS.128 (broadcast within half-warp).
// ============================================================
constexpr int GA_STRIDE = 260;  // floats per k-row of As_dup (1040B, 16B-mult)
constexpr int GB_STRIDE = 100;  // floats per k-row of Bs

__global__ __launch_bounds__(256) void gemm_g(const float* __restrict__ Xr,
                                              const float* __restrict__ Xd)
{
    __shared__ float As[16 * GA_STRIDE];  // [k][2m] duplicated columns
    __shared__ float Bs[16 * GB_STRIDE];  // [k][n]

    const int tid = threadIdx.x;
    const int tx  = tid & 15;      // 16 groups * 6 cols = 96
    const int ty  = tid >> 4;      // 16 groups * 8 rows = 128
    const int bm  = blockIdx.x << 7;

    unsigned long long acc2[8][3];
#pragma unroll
    for (int i = 0; i < 8; i++)
#pragma unroll
        for (int j = 0; j < 3; j++) acc2[i][j] = 0ull;

    for (int t = 0; t < 96; t++) {
        const float* X = (t < 48) ? Xr : Xd;
        const float* W = (t < 48) ? g_Wr : g_Wd;
        const int kb = ((t < 48) ? t : (t - 48)) << 4;

        // A tile: 128 rows x 16 k, duplicated. 512 float4 -> 2/thread.
#pragma unroll
        for (int l = 0; l < 2; l++) {
            int f = tid + (l << 8);
            int r = f >> 2, c4 = f & 3;
            float4 v = *reinterpret_cast<const float4*>(X + (size_t)(bm + r) * 768 + kb + (c4 << 2));
            float* base = &As[(c4 << 2) * GA_STRIDE + (r << 1)];
            *reinterpret_cast<float2*>(base + 0 * GA_STRIDE) = make_float2(v.x, v.x);
            *reinterpret_cast<float2*>(base + 1 * GA_STRIDE) = make_float2(v.y, v.y);
            *reinterpret_cast<float2*>(base + 2 * GA_STRIDE) = make_float2(v.z, v.z);
            *reinterpret_cast<float2*>(base + 3 * GA_STRIDE) = make_float2(v.w, v.w);
        }
        // B tile: 96 rows x 16 k. 384 float4 -> <=2/thread.
#pragma unroll
        for (int l = 0; l < 2; l++) {
            int f = tid + (l << 8);
            if (f < 384) {
                int r = f >> 2, c4 = f & 3;
                float4 v = *reinterpret_cast<const float4*>(W + (size_t)r * 768 + kb + (c4 << 2));
                float* base = &Bs[(c4 << 2) * GB_STRIDE + r];
                base[0 * GB_STRIDE] = v.x;
                base[1 * GB_STRIDE] = v.y;
                base[2 * GB_STRIDE] = v.z;
                base[3 * GB_STRIDE] = v.w;
            }
        }
        __syncthreads();

#pragma unroll
        for (int k = 0; k < 16; k++) {
            unsigned long long ra2[8], rb2[3];
            const ulonglong2* ap =
                reinterpret_cast<const ulonglong2*>(&As[k * GA_STRIDE + (ty << 4)]);
            ulonglong2 u0 = ap[0], u1 = ap[1], u2 = ap[2], u3 = ap[3];
            ra2[0] = u0.x; ra2[1] = u0.y;
            ra2[2] = u1.x; ra2[3] = u1.y;
            ra2[4] = u2.x; ra2[5] = u2.y;
            ra2[6] = u3.x; ra2[7] = u3.y;
#pragma unroll
            for (int j = 0; j < 3; j++)
                rb2[j] = *reinterpret_cast<const unsigned long long*>(
                    &Bs[k * GB_STRIDE + tx * 6 + (j << 1)]);
#pragma unroll
            for (int i = 0; i < 8; i++)
#pragma unroll
                for (int j = 0; j < 3; j++)
                    FMA2(acc2[i][j], ra2[i], rb2[j]);
        }
        __syncthreads();
    }

#pragma unroll
    for (int i = 0; i < 8; i++) {
        int m = bm + (ty << 3) + i;
#pragma unroll
        for (int j = 0; j < 3; j++) {
            int n = tx * 6 + (j << 1);
            float2 r = *reinterpret_cast<float2*>(&acc2[i][j]);
            r.x += g_bg[n];
            r.y += g_bg[n + 1];
            *reinterpret_cast<float2*>(&g_G[(size_t)m * 96 + n]) = r;
        }
    }
}

// ============================================================
// GEMM-out: Y[32768, 768] = G @ g_Wf^T + b_out   (K = 96)
// BM=128, BN=128, BK=16, 256 threads, 8m x 8n tile = 8 x 4 f32x2.
// ============================================================
constexpr int OA_STRIDE = 260;
constexpr int OB_STRIDE = 132;

__global__ __launch_bounds__(256) void gemm_out(const float* __restrict__ bout,
                                                float* __restrict__ Y)
{
    __shared__ float As[16 * OA_STRIDE];  // [k][2m] duplicated
    __shared__ float Bs[16 * OB_STRIDE];  // [k][n]

    const int tid = threadIdx.x;
    const int tx  = tid & 15;
    const int ty  = tid >> 4;
    const int bm  = blockIdx.y << 7;
    const int bn  = blockIdx.x << 7;

    unsigned long long acc2[8][4];
#pragma unroll
    for (int i = 0; i < 8; i++)
#pragma unroll
        for (int j = 0; j < 4; j++) acc2[i][j] = 0ull;

    for (int t = 0; t < 6; t++) {
        const int kt = t << 4;
        // A tile from g_G: 128 rows x 16 k, duplicated. 2 float4/thread.
        // B tile from g_Wf: 128 rows x 16 k. 2 float4/thread.
#pragma unroll
        for (int l = 0; l < 2; l++) {
            int f = tid + (l << 8);
            int r = f >> 2, c4 = f & 3;
            float4 v = *reinterpret_cast<const float4*>(g_G + (size_t)(bm + r) * 96 + kt + (c4 << 2));
            float* abase = &As[(c4 << 2) * OA_STRIDE + (r << 1)];
            *reinterpret_cast<float2*>(abase + 0 * OA_STRIDE) = make_float2(v.x, v.x);
            *reinterpret_cast<float2*>(abase + 1 * OA_STRIDE) = make_float2(v.y, v.y);
            *reinterpret_cast<float2*>(abase + 2 * OA_STRIDE) = make_float2(v.z, v.z);
            *reinterpret_cast<float2*>(abase + 3 * OA_STRIDE) = make_float2(v.w, v.w);
            float4 w = *reinterpret_cast<const float4*>(g_Wf + (size_t)(bn + r) * 96 + kt + (c4 << 2));
            float* bbase = &Bs[(c4 << 2) * OB_STRIDE + r];
            bbase[0 * OB_STRIDE] = w.x;
            bbase[1 * OB_STRIDE] = w.y;
            bbase[2 * OB_STRIDE] = w.z;
            bbase[3 * OB_STRIDE] = w.w;
        }
        __syncthreads();

#pragma unroll
        for (int k = 0; k < 16; k++) {
            unsigned long long ra2[8], rb2[4];
            const ulonglong2* ap =
                reinterpret_cast<const ulonglong2*>(&As[k * OA_STRIDE + (ty << 4)]);
            ulonglong2 u0 = ap[0], u1 = ap[1], u2 = ap[2], u3 = ap[3];
            ra2[0] = u0.x; ra2[1] = u0.y;
            ra2[2] = u1.x; ra2[3] = u1.y;
            ra2[4] = u2.x; ra2[5] = u2.y;
            ra2[6] = u3.x; ra2[7] = u3.y;
            const ulonglong2* bp =
                reinterpret_cast<const ulonglong2*>(&Bs[k * OB_STRIDE + (tx << 3)]);
            ulonglong2 w0 = bp[0], w1 = bp[1];
            rb2[0] = w0.x; rb2[1] = w0.y; rb2[2] = w1.x; rb2[3] = w1.y;
#pragma unroll
            for (int i = 0; i < 8; i++)
#pragma unroll
                for (int j = 0; j < 4; j++)
                    FMA2(acc2[i][j], ra2[i], rb2[j]);
        }
        __syncthreads();
    }

#pragma unroll
    for (int i = 0; i < 8; i++) {
        int m = bm + (ty << 3) + i;
#pragma unroll
        for (int j = 0; j < 4; j++) {
            int n = bn + (tx << 3) + (j << 1);
            float2 r = *reinterpret_cast<float2*>(&acc2[i][j]);
            r.x += bout[n];
            r.y += bout[n + 1];
            *reinterpret_cast<float2*>(&Y[(size_t)m * 768 + n]) = r;
        }
    }
}

// ============================================================
// Copy x_rgb -> first half of output (identity passthrough)
// ============================================================
__global__ void copy_rgb(const float4* __restrict__ src, float4* __restrict__ dst)
{
    size_t i = (size_t)blockIdx.x * blockDim.x + threadIdx.x;
    dst[i] = src[i];
}

// ============================================================
extern "C" void kernel_launch(void* const* d_in, const int* in_sizes, int n_in,
                              void* d_out, int out_size)
{
    const float* x_rgb   = (const float*)d_in[0];
    const float* x_depth = (const float*)d_in[1];
    const float* W1      = (const float*)d_in[2];
    const float* b1      = (const float*)d_in[3];
    const float* W2      = (const float*)d_in[4];
    const float* b2      = (const float*)d_in[5];
    const float* Wout    = (const float*)d_in[6];
    const float* bout    = (const float*)d_in[7];
    const float* aw      = (const float*)d_in[8];

    float* out_rgb = (float*)d_out;
    float* out_fus = out_rgb + (size_t)M_TOK * K_IN;   // second half: x_fusion

    prep_kernel<<<288, 256>>>(W1, b1, W2, b2, Wout, aw);
    gemm_g<<<M_TOK / 128, 256>>>(x_rgb, x_depth);
    gemm_out<<<dim3(K_IN / 128, M_TOK / 128), 256>>>(bout, out_fus);
    copy_rgb<<<(M_TOK * K_IN / 4) / 256, 256>>>((const float4*)x_rgb, (float4*)out_rgb);
}

// round 6
// speedup vs baseline: 2.1766x; 2.1766x over previous
#include <cuda_runtime.h>
#include <cuda_bf16.h>
#include <math.h>
#include <stdint.h>

// Problem constants: B=8, N=4096, C=768, H=8, D=96
constexpr int M_TOK = 8 * 4096;   // 32768 tokens
constexpr int K_IN  = 768;        // C

// ---- device scratch (allocation-free rule: __device__ globals) ----
__device__ __align__(16) __nv_bfloat16 g_Wrh[96 * 768];  // hi(w1*sum_h Wv_rgb)
__device__ __align__(16) __nv_bfloat16 g_Wrl[96 * 768];  // lo
__device__ __align__(16) __nv_bfloat16 g_Wdh[96 * 768];  // hi(w0*sum_h Wv_depth)
__device__ __align__(16) __nv_bfloat16 g_Wdl[96 * 768];
__device__ __align__(16) __nv_bfloat16 g_Wfh[768 * 96];  // hi(sum_q Wout folded)
__device__ __align__(16) __nv_bfloat16 g_Wfl[768 * 96];
__device__ float g_bg[96];                                // combined bias for g
__device__ __align__(16) __nv_bfloat16 g_Gh[32768 * 96];  // intermediate G hi
__device__ __align__(16) __nv_bfloat16 g_Gl[32768 * 96];  // intermediate G lo

// ============================================================
// Helpers (plain sm_103-safe PTX: ldmatrix + mma.sync bf16)
// ============================================================
__device__ __forceinline__ uint32_t smem_u32(const void* p) {
    uint32_t a;
    asm("{ .reg .u64 t; cvta.to.shared.u64 t, %1; cvt.u32.u64 %0, t; }" : "=r"(a) : "l"(p));
    return a;
}
__device__ __forceinline__ void ldsm4(uint32_t* r, uint32_t addr) {
    asm volatile("ldmatrix.sync.aligned.m8n8.x4.shared.b16 {%0,%1,%2,%3}, [%4];"
                 : "=r"(r[0]), "=r"(r[1]), "=r"(r[2]), "=r"(r[3]) : "r"(addr));
}
__device__ __forceinline__ void mma16816(float* c, const uint32_t* a, const uint32_t* b) {
    asm volatile(
        "mma.sync.aligned.m16n8k16.row.col.f32.bf16.bf16.f32 "
        "{%0,%1,%2,%3}, {%4,%5,%6,%7}, {%8,%9}, {%0,%1,%2,%3};"
        : "+f"(c[0]), "+f"(c[1]), "+f"(c[2]), "+f"(c[3])
        : "r"(a[0]), "r"(a[1]), "r"(a[2]), "r"(a[3]), "r"(b[0]), "r"(b[1]));
}
__device__ __forceinline__ uint32_t packbf2(__nv_bfloat16 a, __nv_bfloat16 b) {
    __nv_bfloat162 t; t.x = a; t.y = b;
    return *reinterpret_cast<uint32_t*>(&t);
}
__device__ __forceinline__ void splitbf(float v, __nv_bfloat16& h, __nv_bfloat16& l) {
    h = __float2bfloat16_rn(v);
    l = __float2bfloat16_rn(v - __bfloat162float(h));
}
// XOR swizzle on 16B chunks: conflict-free ldmatrix for row strides == 4 (mod 8) chunks
__device__ __forceinline__ uint32_t swz(uint32_t row, uint32_t chunk) {
    return chunk ^ ((row >> 1) & 3);
}

// ============================================================
// Prep: fold heads, sigmoid weights, split to bf16 hi/lo
// ============================================================
__global__ void prep_kernel(const float* __restrict__ W1, const float* __restrict__ b1,
                            const float* __restrict__ W2, const float* __restrict__ b2,
                            const float* __restrict__ Wout, const float* __restrict__ aw)
{
    int idx = blockIdx.x * blockDim.x + threadIdx.x;   // 0 .. 73727
    float w0 = 1.0f / (1.0f + expf(-aw[0]));
    float w1 = 1.0f / (1.0f + expf(-aw[1]));

    if (idx < 96 * 768) {
        int d = idx / 768;
        int c = idx - d * 768;
        float sr = 0.0f, sd = 0.0f;
#pragma unroll
        for (int h = 0; h < 8; h++) {
            sr += W1[(size_t)(1536 + h * 96 + d) * 768 + c];
            sd += W2[(size_t)(768  + h * 96 + d) * 768 + c];
        }
        __nv_bfloat16 h16, l16;
        splitbf(w1 * sr, h16, l16); g_Wrh[idx] = h16; g_Wrl[idx] = l16;
        splitbf(w0 * sd, h16, l16); g_Wdh[idx] = h16; g_Wdl[idx] = l16;
    }
    if (idx < 768 * 96) {
        int c = idx / 96;
        int d = idx - c * 96;
        float s = 0.0f;
#pragma unroll
        for (int q = 0; q < 8; q++) s += Wout[(size_t)c * 768 + q * 96 + d];
        __nv_bfloat16 h16, l16;
        splitbf(s, h16, l16); g_Wfh[idx] = h16; g_Wfl[idx] = l16;
    }
    if (idx < 96) {
        float sbr = 0.0f, sbd = 0.0f;
#pragma unroll
        for (int h = 0; h < 8; h++) {
            sbr += b1[1536 + h * 96 + idx];
            sbd += b2[768  + h * 96 + idx];
        }
        g_bg[idx] = w0 * sbd + w1 * sbr;
    }
}

// ============================================================
// GEMM-G: G[32768,96] = Xr@Wr^T + Xd@Wd^T + bg  (virtual K=1536)
// CTA 128x96, BK=32, double-buffered. 8 warps (4m x 2n),
// warp tile 32x48. bf16 hi/lo 3-term mma.sync.
// smem stage: Ah 8K | Al 8K | Bh 6K | Bl 6K = 28672 B, x2 stages.
// ============================================================
constexpr uint32_t GST  = 28672;
constexpr uint32_t G_AL = 8192, G_BH = 16384, G_BL = 22528;
constexpr int G_STAGES  = 48;   // 1536 / 32

__global__ __launch_bounds__(256, 1) void gemm_g(const float* __restrict__ Xr,
                                                 const float* __restrict__ Xd)
{
    extern __shared__ char dsm[];
    const uint32_t sbase = smem_u32(dsm);

    const int tid   = threadIdx.x;
    const int lane  = tid & 31;
    const int wid   = tid >> 5;
    const int warpM = wid >> 1;      // 0..3
    const int warpN = wid & 1;       // 0..1
    const int bm    = blockIdx.x << 7;

    float acc[2][6][4];
#pragma unroll
    for (int i = 0; i < 2; i++)
#pragma unroll
        for (int j = 0; j < 6; j++)
#pragma unroll
            for (int q = 0; q < 4; q++) acc[i][j][q] = 0.0f;

    // ---- per-thread load geometry (invariant) ----
    const int arow0 = tid >> 3;          // + 32*l  (A: 128 rows x 8 float4-cols)
    const int ac4   = tid & 7;           // k-group of 4 floats
    const int brow0 = tid >> 3;          // + 32*l, l<3 (B: 96 rows x 8 uint2-cols)
    const int bu    = tid & 7;           // k-group of 4 bf16

    // A STS byte offset (row-dependent part added per l; swizzle invariant in l)
    const uint32_t a_sts_sw = (swz((uint32_t)arow0, (uint32_t)(ac4 >> 1)) << 4) + (ac4 & 1) * 8;
    const uint32_t b_sts_sw = (swz((uint32_t)brow0, (uint32_t)(bu >> 1)) << 4) + (bu & 1) * 8;

    // ---- ldmatrix per-lane addresses (byte offsets within a stage) ----
    // A: row = warpM*32 + mt*16 + (lane&15), chunk = kk*2 + (lane>>4)
    const uint32_t a_row = (uint32_t)(warpM * 32 + (lane & 15));
    const uint32_t a_ck0 = (uint32_t)(lane >> 4);
    // B: n_row = warpN*48 + ng*16 + (lane&7) + ((lane>>4)<<3), chunk = kk*2 + ((lane>>3)&1)
    const uint32_t b_row = (uint32_t)(warpN * 48 + (lane & 7) + ((lane >> 4) << 3));
    const uint32_t b_ck0 = (uint32_t)((lane >> 3) & 1);

    float4 av[4];
    uint2  bhv[3], blv[3];

    // ---- prologue: fetch stage 0 ----
    {
        const float* X = Xr;
#pragma unroll
        for (int l = 0; l < 4; l++)
            av[l] = *reinterpret_cast<const float4*>(
                X + (size_t)(bm + arow0 + 32 * l) * 768 + (ac4 << 2));
#pragma unroll
        for (int l = 0; l < 3; l++) {
            size_t gi = (size_t)(brow0 + 32 * l) * 768 + (bu << 2);
            bhv[l] = *reinterpret_cast<const uint2*>(g_Wrh + gi);
            blv[l] = *reinterpret_cast<const uint2*>(g_Wrl + gi);
        }
    }
    // STS stage 0 into buf 0
    {
        char* st = dsm;
#pragma unroll
        for (int l = 0; l < 4; l++) {
            uint32_t ro = (uint32_t)(arow0 + 32 * l) * 64;
            __nv_bfloat16 h0, h1, h2, h3, l0, l1, l2, l3;
            splitbf(av[l].x, h0, l0); splitbf(av[l].y, h1, l1);
            splitbf(av[l].z, h2, l2); splitbf(av[l].w, h3, l3);
            *reinterpret_cast<uint2*>(st + ro + a_sts_sw) =
                make_uint2(packbf2(h0, h1), packbf2(h2, h3));
            *reinterpret_cast<uint2*>(st + G_AL + ro + a_sts_sw) =
                make_uint2(packbf2(l0, l1), packbf2(l2, l3));
        }
#pragma unroll
        for (int l = 0; l < 3; l++) {
            uint32_t ro = (uint32_t)(brow0 + 32 * l) * 64;
            *reinterpret_cast<uint2*>(st + G_BH + ro + b_sts_sw) = bhv[l];
            *reinterpret_cast<uint2*>(st + G_BL + ro + b_sts_sw) = blv[l];
        }
    }
    __syncthreads();

    for (int s = 0; s < G_STAGES; s++) {
        // ---- prefetch stage s+1 ----
        if (s + 1 < G_STAGES) {
            const int sn = s + 1;
            const float* X = (sn < 24) ? Xr : Xd;
            const __nv_bfloat16* BH = (sn < 24) ? g_Wrh : g_Wdh;
            const __nv_bfloat16* BL = (sn < 24) ? g_Wrl : g_Wdl;
            const int kb = ((sn < 24) ? sn : (sn - 24)) << 5;
#pragma unroll
            for (int l = 0; l < 4; l++)
                av[l] = *reinterpret_cast<const float4*>(
                    X + (size_t)(bm + arow0 + 32 * l) * 768 + kb + (ac4 << 2));
#pragma unroll
            for (int l = 0; l < 3; l++) {
                size_t gi = (size_t)(brow0 + 32 * l) * 768 + kb + (bu << 2);
                bhv[l] = *reinterpret_cast<const uint2*>(BH + gi);
                blv[l] = *reinterpret_cast<const uint2*>(BL + gi);
            }
        }

        // ---- compute stage s from buf (s&1) ----
        {
            const uint32_t sb = sbase + (uint32_t)(s & 1) * GST;
#pragma unroll
            for (int kk = 0; kk < 2; kk++) {
                uint32_t ah[2][4], al[2][4];
#pragma unroll
                for (int mt = 0; mt < 2; mt++) {
                    uint32_t row = a_row + mt * 16;
                    uint32_t addr = sb + row * 64 + (swz(row, kk * 2 + a_ck0) << 4);
                    ldsm4(ah[mt], addr);
                    ldsm4(al[mt], addr + G_AL);
                }
                uint32_t bh2[3][4], bl2[3][4];
#pragma unroll
                for (int ng = 0; ng < 3; ng++) {
                    uint32_t row = b_row + ng * 16;
                    uint32_t addr = sb + G_BH + row * 64 + (swz(row, kk * 2 + b_ck0) << 4);
                    ldsm4(bh2[ng], addr);
                    ldsm4(bl2[ng], addr + (G_BL - G_BH));
                }
#pragma unroll
                for (int mt = 0; mt < 2; mt++)
#pragma unroll
                    for (int nt = 0; nt < 6; nt++) {
                        const uint32_t* bh = &bh2[nt >> 1][(nt & 1) * 2];
                        const uint32_t* bl = &bl2[nt >> 1][(nt & 1) * 2];
                        mma16816(acc[mt][nt], ah[mt], bh);
                        mma16816(acc[mt][nt], ah[mt], bl);
                        mma16816(acc[mt][nt], al[mt], bh);
                    }
            }
        }

        // ---- store stage s+1 into buf ((s+1)&1) ----
        if (s + 1 < G_STAGES) {
            char* st = dsm + ((s + 1) & 1) * GST;
#pragma unroll
            for (int l = 0; l < 4; l++) {
                uint32_t ro = (uint32_t)(arow0 + 32 * l) * 64;
                __nv_bfloat16 h0, h1, h2, h3, l0, l1, l2, l3;
                splitbf(av[l].x, h0, l0); splitbf(av[l].y, h1, l1);
                splitbf(av[l].z, h2, l2); splitbf(av[l].w, h3, l3);
                *reinterpret_cast<uint2*>(st + ro + a_sts_sw) =
                    make_uint2(packbf2(h0, h1), packbf2(h2, h3));
                *reinterpret_cast<uint2*>(st + G_AL + ro + a_sts_sw) =
                    make_uint2(packbf2(l0, l1), packbf2(l2, l3));
            }
#pragma unroll
            for (int l = 0; l < 3; l++) {
                uint32_t ro = (uint32_t)(brow0 + 32 * l) * 64;
                *reinterpret_cast<uint2*>(st + G_BH + ro + b_sts_sw) = bhv[l];
                *reinterpret_cast<uint2*>(st + G_BL + ro + b_sts_sw) = blv[l];
            }
        }
        __syncthreads();
    }

    // ---- epilogue: add bias, split to bf16 hi/lo, write G ----
#pragma unroll
    for (int mt = 0; mt < 2; mt++) {
        int m0 = bm + warpM * 32 + mt * 16 + (lane >> 2);
#pragma unroll
        for (int nt = 0; nt < 6; nt++) {
            int n = warpN * 48 + nt * 8 + (lane & 3) * 2;
            float b0 = g_bg[n], b1 = g_bg[n + 1];
            float v0 = acc[mt][nt][0] + b0, v1 = acc[mt][nt][1] + b1;
            float v2 = acc[mt][nt][2] + b0, v3 = acc[mt][nt][3] + b1;
            __nv_bfloat16 h0, l0, h1, l1;
            splitbf(v0, h0, l0); splitbf(v1, h1, l1);
            *reinterpret_cast<uint32_t*>(g_Gh + (size_t)m0 * 96 + n) = packbf2(h0, h1);
            *reinterpret_cast<uint32_t*>(g_Gl + (size_t)m0 * 96 + n) = packbf2(l0, l1);
            splitbf(v2, h0, l0); splitbf(v3, h1, l1);
            *reinterpret_cast<uint32_t*>(g_Gh + (size_t)(m0 + 8) * 96 + n) = packbf2(h0, h1);
            *reinterpret_cast<uint32_t*>(g_Gl + (size_t)(m0 + 8) * 96 + n) = packbf2(l0, l1);
        }
    }
}

// ============================================================
// GEMM-out: Y[32768,768] = G @ Wf^T + bout  (K=96, single smem load)
// CTA 128x128, 8 warps (4m x 2n), warp tile 32x64.
// smem: Ah 24K | Al 24K | Bh 24K | Bl 24K = 96 KB (rows of 192B).
// ============================================================
constexpr uint32_t O_AL = 24576, O_BH = 49152, O_BL = 73728;

__global__ __launch_bounds__(256, 1) void gemm_out(const float* __restrict__ bout,
                                                   float* __restrict__ Y)
{
    extern __shared__ char dsm[];
    const uint32_t sbase = smem_u32(dsm);

    const int tid   = threadIdx.x;
    const int lane  = tid & 31;
    const int wid   = tid >> 5;
    const int warpM = wid >> 1;
    const int warpN = wid & 1;
    const int bm    = blockIdx.y << 7;
    const int bn    = blockIdx.x << 7;

    // ---- load A (G rows bm..bm+127) and B (Wf rows bn..bn+127), hi+lo ----
    // 128 rows x 24 uint2 per matrix = 3072 units; 12 per thread.
    for (int l = 0; l < 12; l++) {
        int f = tid + (l << 8);
        int r = f / 24, u = f - r * 24;
        size_t ga = (size_t)(bm + r) * 96 + (u << 2);
        size_t gb = (size_t)(bn + r) * 96 + (u << 2);
        uint32_t so = (uint32_t)r * 192 + (swz((uint32_t)r, (uint32_t)(u >> 1)) << 4) + (u & 1) * 8;
        *reinterpret_cast<uint2*>(dsm + so)        = *reinterpret_cast<const uint2*>(g_Gh + ga);
        *reinterpret_cast<uint2*>(dsm + O_AL + so) = *reinterpret_cast<const uint2*>(g_Gl + ga);
        *reinterpret_cast<uint2*>(dsm + O_BH + so) = *reinterpret_cast<const uint2*>(g_Wfh + gb);
        *reinterpret_cast<uint2*>(dsm + O_BL + so) = *reinterpret_cast<const uint2*>(g_Wfl + gb);
    }
    __syncthreads();

    float acc[2][8][4];
#pragma unroll
    for (int i = 0; i < 2; i++)
#pragma unroll
        for (int j = 0; j < 8; j++)
#pragma unroll
            for (int q = 0; q < 4; q++) acc[i][j][q] = 0.0f;

    const uint32_t a_row = (uint32_t)(warpM * 32 + (lane & 15));
    const uint32_t a_ck0 = (uint32_t)(lane >> 4);
    const uint32_t b_row = (uint32_t)(warpN * 64 + (lane & 7) + ((lane >> 4) << 3));
    const uint32_t b_ck0 = (uint32_t)((lane >> 3) & 1);

#pragma unroll
    for (int ks = 0; ks < 6; ks++) {
        uint32_t ah[2][4], al[2][4];
#pragma unroll
        for (int mt = 0; mt < 2; mt++) {
            uint32_t row = a_row + mt * 16;
            uint32_t addr = sbase + row * 192 + (swz(row, ks * 2 + a_ck0) << 4);
            ldsm4(ah[mt], addr);
            ldsm4(al[mt], addr + O_AL);
        }
        uint32_t bh2[4][4], bl2[4][4];
#pragma unroll
        for (int ng = 0; ng < 4; ng++) {
            uint32_t row = b_row + ng * 16;
            uint32_t addr = sbase + O_BH + row * 192 + (swz(row, ks * 2 + b_ck0) << 4);
            ldsm4(bh2[ng], addr);
            ldsm4(bl2[ng], addr + (O_BL - O_BH));
        }
#pragma unroll
        for (int mt = 0; mt < 2; mt++)
#pragma unroll
            for (int nt = 0; nt < 8; nt++) {
                const uint32_t* bh = &bh2[nt >> 1][(nt & 1) * 2];
                const uint32_t* bl = &bl2[nt >> 1][(nt & 1) * 2];
                mma16816(acc[mt][nt], ah[mt], bh);
                mma16816(acc[mt][nt], ah[mt], bl);
                mma16816(acc[mt][nt], al[mt], bh);
            }
    }

    // ---- epilogue: add bias, write Y ----
#pragma unroll
    for (int mt = 0; mt < 2; mt++) {
        int m0 = bm + warpM * 32 + mt * 16 + (lane >> 2);
#pragma unroll
        for (int nt = 0; nt < 8; nt++) {
            int n = bn + warpN * 64 + nt * 8 + (lane & 3) * 2;
            float b0 = bout[n], b1 = bout[n + 1];
            *reinterpret_cast<float2*>(Y + (size_t)m0 * 768 + n) =
                make_float2(acc[mt][nt][0] + b0, acc[mt][nt][1] + b1);
            *reinterpret_cast<float2*>(Y + (size_t)(m0 + 8) * 768 + n) =
                make_float2(acc[mt][nt][2] + b0, acc[mt][nt][3] + b1);
        }
    }
}

// ============================================================
// Copy x_rgb -> first half of output (identity passthrough)
// ============================================================
__global__ void copy_rgb(const float4* __restrict__ src, float4* __restrict__ dst)
{
    size_t i = (size_t)blockIdx.x * blockDim.x + threadIdx.x;
    dst[i] = src[i];
}

// ============================================================
extern "C" void kernel_launch(void* const* d_in, const int* in_sizes, int n_in,
                              void* d_out, int out_size)
{
    const float* x_rgb   = (const float*)d_in[0];
    const float* x_depth = (const float*)d_in[1];
    const float* W1      = (const float*)d_in[2];
    const float* b1      = (const float*)d_in[3];
    const float* W2      = (const float*)d_in[4];
    const float* b2      = (const float*)d_in[5];
    const float* Wout    = (const float*)d_in[6];
    const float* bout    = (const float*)d_in[7];
    const float* aw      = (const float*)d_in[8];

    float* out_rgb = (float*)d_out;
    float* out_fus = out_rgb + (size_t)M_TOK * K_IN;   // second half: x_fusion

    static bool attr_done = false;
    if (!attr_done) {
        cudaFuncSetAttribute(gemm_g,   cudaFuncAttributeMaxDynamicSharedMemorySize, 2 * GST);
        cudaFuncSetAttribute(gemm_out, cudaFuncAttributeMaxDynamicSharedMemorySize, 98304);
        attr_done = true;
    }

    prep_kernel<<<288, 256>>>(W1, b1, W2, b2, Wout, aw);
    gemm_g<<<M_TOK / 128, 256, 2 * GST>>>(x_rgb, x_depth);
    gemm_out<<<dim3(K_IN / 128, M_TOK / 128), 256, 98304>>>(bout, out_fus);
    copy_rgb<<<(M_TOK * K_IN / 4) / 256, 256>>>((const float4*)x_rgb, (float4*)out_rgb);
}

// round 7
// speedup vs baseline: 2.7337x; 1.2559x over previous
#include <cuda_runtime.h>
#include <cuda_bf16.h>
#include <math.h>
#include <stdint.h>

// Problem constants: B=8, N=4096, C=768, H=8, D=96
constexpr int M_TOK = 8 * 4096;   // 32768 tokens
constexpr int K_IN  = 768;        // C

// ---- device scratch (allocation-free rule: __device__ globals) ----
__device__ __align__(16) __nv_bfloat16 g_Wrh[96 * 768];  // hi(w1*sum_h Wv_rgb)
__device__ __align__(16) __nv_bfloat16 g_Wrl[96 * 768];  // lo
__device__ __align__(16) __nv_bfloat16 g_Wdh[96 * 768];  // hi(w0*sum_h Wv_depth)
__device__ __align__(16) __nv_bfloat16 g_Wdl[96 * 768];
__device__ __align__(16) __nv_bfloat16 g_Wfh[768 * 96];  // hi(sum_q Wout folded)
__device__ __align__(16) __nv_bfloat16 g_Wfl[768 * 96];
__device__ float g_bg[96];                                // combined bias for g
__device__ __align__(16) __nv_bfloat16 g_Gh[32768 * 96];  // intermediate G hi
__device__ __align__(16) __nv_bfloat16 g_Gl[32768 * 96];  // intermediate G lo

// ============================================================
// Helpers (plain sm_103-safe PTX: ldmatrix + mma.sync + cp.async)
// ============================================================
__device__ __forceinline__ uint32_t smem_u32(const void* p) {
    uint32_t a;
    asm("{ .reg .u64 t; cvta.to.shared.u64 t, %1; cvt.u32.u64 %0, t; }" : "=r"(a) : "l"(p));
    return a;
}
__device__ __forceinline__ void ldsm4(uint32_t* r, uint32_t addr) {
    asm volatile("ldmatrix.sync.aligned.m8n8.x4.shared.b16 {%0,%1,%2,%3}, [%4];"
                 : "=r"(r[0]), "=r"(r[1]), "=r"(r[2]), "=r"(r[3]) : "r"(addr));
}
__device__ __forceinline__ void mma16816(float* c, const uint32_t* a, const uint32_t* b) {
    asm volatile(
        "mma.sync.aligned.m16n8k16.row.col.f32.bf16.bf16.f32 "
        "{%0,%1,%2,%3}, {%4,%5,%6,%7}, {%8,%9}, {%0,%1,%2,%3};"
        : "+f"(c[0]), "+f"(c[1]), "+f"(c[2]), "+f"(c[3])
        : "r"(a[0]), "r"(a[1]), "r"(a[2]), "r"(a[3]), "r"(b[0]), "r"(b[1]));
}
__device__ __forceinline__ void cpa8(uint32_t d, const void* s) {
    asm volatile("cp.async.ca.shared.global [%0], [%1], 8;" :: "r"(d), "l"(s));
}
__device__ __forceinline__ void cpa16(uint32_t d, const void* s) {
    asm volatile("cp.async.cg.shared.global [%0], [%1], 16;" :: "r"(d), "l"(s));
}
#define CPA_COMMIT() asm volatile("cp.async.commit_group;" ::: "memory")
#define CPA_WAIT0()  asm volatile("cp.async.wait_group 0;" ::: "memory")

__device__ __forceinline__ uint32_t packbf2(__nv_bfloat16 a, __nv_bfloat16 b) {
    __nv_bfloat162 t; t.x = a; t.y = b;
    return *reinterpret_cast<uint32_t*>(&t);
}
__device__ __forceinline__ void splitbf(float v, __nv_bfloat16& h, __nv_bfloat16& l) {
    h = __float2bfloat16_rn(v);
    l = __float2bfloat16_rn(v - __bfloat162float(h));
}
// XOR swizzle on 16B chunks: conflict-free ldmatrix for 64B/192B rows
__device__ __forceinline__ uint32_t swz(uint32_t row, uint32_t chunk) {
    return chunk ^ ((row >> 1) & 3);
}

// ============================================================
// Prep: fold heads, sigmoid weights, split to bf16 hi/lo
// ============================================================
__global__ void prep_kernel(const float* __restrict__ W1, const float* __restrict__ b1,
                            const float* __restrict__ W2, const float* __restrict__ b2,
                            const float* __restrict__ Wout, const float* __restrict__ aw)
{
    int idx = blockIdx.x * blockDim.x + threadIdx.x;   // 0 .. 73727
    float w0 = 1.0f / (1.0f + expf(-aw[0]));
    float w1 = 1.0f / (1.0f + expf(-aw[1]));

    if (idx < 96 * 768) {
        int d = idx / 768;
        int c = idx - d * 768;
        float sr = 0.0f, sd = 0.0f;
#pragma unroll
        for (int h = 0; h < 8; h++) {
            sr += W1[(size_t)(1536 + h * 96 + d) * 768 + c];
            sd += W2[(size_t)(768  + h * 96 + d) * 768 + c];
        }
        __nv_bfloat16 h16, l16;
        splitbf(w1 * sr, h16, l16); g_Wrh[idx] = h16; g_Wrl[idx] = l16;
        splitbf(w0 * sd, h16, l16); g_Wdh[idx] = h16; g_Wdl[idx] = l16;
    }
    if (idx < 768 * 96) {
        int c = idx / 96;
        int d = idx - c * 96;
        float s = 0.0f;
#pragma unroll
        for (int q = 0; q < 8; q++) s += Wout[(size_t)c * 768 + q * 96 + d];
        __nv_bfloat16 h16, l16;
        splitbf(s, h16, l16); g_Wfh[idx] = h16; g_Wfl[idx] = l16;
    }
    if (idx < 96) {
        float sbr = 0.0f, sbd = 0.0f;
#pragma unroll
        for (int h = 0; h < 8; h++) {
            sbr += b1[1536 + h * 96 + idx];
            sbd += b2[768  + h * 96 + idx];
        }
        g_bg[idx] = w0 * sbd + w1 * sbr;
    }
}

// ============================================================
// GEMM-G: G[32768,96] = Xr@Wr^T + Xd@Wd^T + bg  (virtual K=1536)
// CTA 128x96, BK=32, double-buffered; cp.async for B tiles.
// ALSO writes the x_rgb passthrough copy (fused; X read exactly once).
// ============================================================
constexpr uint32_t GST  = 28672;
constexpr uint32_t G_AL = 8192, G_BH = 16384, G_BL = 22528;
constexpr int G_STAGES  = 48;   // 1536 / 32

__global__ __launch_bounds__(256, 1) void gemm_g(const float* __restrict__ Xr,
                                                 const float* __restrict__ Xd,
                                                 float* __restrict__ out_rgb)
{
    extern __shared__ char dsm[];
    const uint32_t sbase = smem_u32(dsm);

    const int tid   = threadIdx.x;
    const int lane  = tid & 31;
    const int wid   = tid >> 5;
    const int warpM = wid >> 1;      // 0..3
    const int warpN = wid & 1;       // 0..1
    const int bm    = blockIdx.x << 7;

    float acc[2][6][4];
#pragma unroll
    for (int i = 0; i < 2; i++)
#pragma unroll
        for (int j = 0; j < 6; j++)
#pragma unroll
            for (int q = 0; q < 4; q++) acc[i][j][q] = 0.0f;

    const int arow0 = tid >> 3;          // + 32*l  (A: 128 rows x 8 float4-cols)
    const int ac4   = tid & 7;
    const int brow0 = tid >> 3;          // + 32*l, l<3 (B: 96 rows x 8 uint2-cols)
    const int bu    = tid & 7;

    const uint32_t a_sts_sw = (swz((uint32_t)arow0, (uint32_t)(ac4 >> 1)) << 4) + (ac4 & 1) * 8;
    const uint32_t b_sts_sw = (swz((uint32_t)brow0, (uint32_t)(bu >> 1)) << 4) + (bu & 1) * 8;

    const uint32_t a_row = (uint32_t)(warpM * 32 + (lane & 15));
    const uint32_t a_ck0 = (uint32_t)(lane >> 4);
    const uint32_t b_row = (uint32_t)(warpN * 48 + (lane & 7) + ((lane >> 4) << 3));
    const uint32_t b_ck0 = (uint32_t)((lane >> 3) & 1);

    float4 av[4];

    // ---- prologue: stage 0 (rgb, kb = 0) ----
#pragma unroll
    for (int l = 0; l < 4; l++)
        av[l] = *reinterpret_cast<const float4*>(
            Xr + (size_t)(bm + arow0 + 32 * l) * 768 + (ac4 << 2));
#pragma unroll
    for (int l = 0; l < 3; l++) {
        uint32_t row = (uint32_t)(brow0 + 32 * l);
        const __nv_bfloat16* sh = g_Wrh + (size_t)row * 768 + (bu << 2);
        const __nv_bfloat16* sl = g_Wrl + (size_t)row * 768 + (bu << 2);
        cpa8(sbase + G_BH + row * 64 + b_sts_sw, sh);
        cpa8(sbase + G_BL + row * 64 + b_sts_sw, sl);
    }
    CPA_COMMIT();
    {
        char* st = dsm;
#pragma unroll
        for (int l = 0; l < 4; l++) {
            uint32_t ro = (uint32_t)(arow0 + 32 * l) * 64;
            __nv_bfloat16 h0, h1, h2, h3, l0, l1, l2, l3;
            splitbf(av[l].x, h0, l0); splitbf(av[l].y, h1, l1);
            splitbf(av[l].z, h2, l2); splitbf(av[l].w, h3, l3);
            *reinterpret_cast<uint2*>(st + ro + a_sts_sw) =
                make_uint2(packbf2(h0, h1), packbf2(h2, h3));
            *reinterpret_cast<uint2*>(st + G_AL + ro + a_sts_sw) =
                make_uint2(packbf2(l0, l1), packbf2(l2, l3));
            // fused x_rgb passthrough (stage 0 slice)
            *reinterpret_cast<float4*>(
                out_rgb + (size_t)(bm + arow0 + 32 * l) * 768 + (ac4 << 2)) = av[l];
        }
    }
    CPA_WAIT0();
    __syncthreads();

    for (int s = 0; s < G_STAGES; s++) {
        const int sn = s + 1;
        // ---- prefetch stage s+1: A via LDG, B via cp.async ----
        if (sn < G_STAGES) {
            const float* X = (sn < 24) ? Xr : Xd;
            const __nv_bfloat16* BH = (sn < 24) ? g_Wrh : g_Wdh;
            const __nv_bfloat16* BL = (sn < 24) ? g_Wrl : g_Wdl;
            const int kb = ((sn < 24) ? sn : (sn - 24)) << 5;
            const uint32_t bo = (uint32_t)(sn & 1) * GST;
#pragma unroll
            for (int l = 0; l < 4; l++)
                av[l] = *reinterpret_cast<const float4*>(
                    X + (size_t)(bm + arow0 + 32 * l) * 768 + kb + (ac4 << 2));
#pragma unroll
            for (int l = 0; l < 3; l++) {
                uint32_t row = (uint32_t)(brow0 + 32 * l);
                size_t gi = (size_t)row * 768 + kb + (bu << 2);
                cpa8(sbase + bo + G_BH + row * 64 + b_sts_sw, BH + gi);
                cpa8(sbase + bo + G_BL + row * 64 + b_sts_sw, BL + gi);
            }
            CPA_COMMIT();
        }

        // ---- compute stage s ----
        {
            const uint32_t sb = sbase + (uint32_t)(s & 1) * GST;
#pragma unroll
            for (int kk = 0; kk < 2; kk++) {
                uint32_t ah[2][4], al[2][4];
#pragma unroll
                for (int mt = 0; mt < 2; mt++) {
                    uint32_t row = a_row + mt * 16;
                    uint32_t addr = sb + row * 64 + (swz(row, kk * 2 + a_ck0) << 4);
                    ldsm4(ah[mt], addr);
                    ldsm4(al[mt], addr + G_AL);
                }
                uint32_t bh2[3][4], bl2[3][4];
#pragma unroll
                for (int ng = 0; ng < 3; ng++) {
                    uint32_t row = b_row + ng * 16;
                    uint32_t addr = sb + G_BH + row * 64 + (swz(row, kk * 2 + b_ck0) << 4);
                    ldsm4(bh2[ng], addr);
                    ldsm4(bl2[ng], addr + (G_BL - G_BH));
                }
#pragma unroll
                for (int mt = 0; mt < 2; mt++)
#pragma unroll
                    for (int nt = 0; nt < 6; nt++) {
                        const uint32_t* bh = &bh2[nt >> 1][(nt & 1) * 2];
                        const uint32_t* bl = &bl2[nt >> 1][(nt & 1) * 2];
                        mma16816(acc[mt][nt], ah[mt], bh);
                        mma16816(acc[mt][nt], ah[mt], bl);
                        mma16816(acc[mt][nt], al[mt], bh);
                    }
            }
        }

        // ---- STS stage s+1 (+ fused copy for rgb stages) ----
        if (sn < G_STAGES) {
            char* st = dsm + (sn & 1) * GST;
            const int kb = ((sn < 24) ? sn : (sn - 24)) << 5;
#pragma unroll
            for (int l = 0; l < 4; l++) {
                uint32_t ro = (uint32_t)(arow0 + 32 * l) * 64;
                __nv_bfloat16 h0, h1, h2, h3, l0, l1, l2, l3;
                splitbf(av[l].x, h0, l0); splitbf(av[l].y, h1, l1);
                splitbf(av[l].z, h2, l2); splitbf(av[l].w, h3, l3);
                *reinterpret_cast<uint2*>(st + ro + a_sts_sw) =
                    make_uint2(packbf2(h0, h1), packbf2(h2, h3));
                *reinterpret_cast<uint2*>(st + G_AL + ro + a_sts_sw) =
                    make_uint2(packbf2(l0, l1), packbf2(l2, l3));
            }
            if (sn < 24) {
#pragma unroll
                for (int l = 0; l < 4; l++)
                    *reinterpret_cast<float4*>(
                        out_rgb + (size_t)(bm + arow0 + 32 * l) * 768 + kb + (ac4 << 2)) = av[l];
            }
            CPA_WAIT0();
        }
        __syncthreads();
    }

    // ---- epilogue: add bias, split to bf16 hi/lo, write G ----
#pragma unroll
    for (int mt = 0; mt < 2; mt++) {
        int m0 = bm + warpM * 32 + mt * 16 + (lane >> 2);
#pragma unroll
        for (int nt = 0; nt < 6; nt++) {
            int n = warpN * 48 + nt * 8 + (lane & 3) * 2;
            float b0 = g_bg[n], b1 = g_bg[n + 1];
            float v0 = acc[mt][nt][0] + b0, v1 = acc[mt][nt][1] + b1;
            float v2 = acc[mt][nt][2] + b0, v3 = acc[mt][nt][3] + b1;
            __nv_bfloat16 h0, l0, h1, l1;
            splitbf(v0, h0, l0); splitbf(v1, h1, l1);
            *reinterpret_cast<uint32_t*>(g_Gh + (size_t)m0 * 96 + n) = packbf2(h0, h1);
            *reinterpret_cast<uint32_t*>(g_Gl + (size_t)m0 * 96 + n) = packbf2(l0, l1);
            splitbf(v2, h0, l0); splitbf(v3, h1, l1);
            *reinterpret_cast<uint32_t*>(g_Gh + (size_t)(m0 + 8) * 96 + n) = packbf2(h0, h1);
            *reinterpret_cast<uint32_t*>(g_Gl + (size_t)(m0 + 8) * 96 + n) = packbf2(l0, l1);
        }
    }
}

// ============================================================
// GEMM-out: Y[32768,768] = G @ Wf^T + bout  (K=96)
// 256 CTAs; each loads its G block (Ah/Al) ONCE into smem, then
// loops over all 6 Wf tiles with a cp.async double-buffered pipeline.
// smem: A 48K | Bbuf0 48K | Bbuf1 48K = 144 KB.
// ============================================================
constexpr uint32_t O_AL  = 24576;   // Al offset within A region
constexpr uint32_t O_B   = 49152;   // B buffers start
constexpr uint32_t O_BSZ = 49152;   // per B buffer (Bh 24K + Bl 24K)
constexpr uint32_t O_BL  = 24576;   // Bl offset within a B buffer
constexpr int O_SMEM = 147456;

__global__ __launch_bounds__(256, 1) void gemm_out(const float* __restrict__ bout,
                                                   float* __restrict__ Y)
{
    extern __shared__ char dsm[];
    const uint32_t sbase = smem_u32(dsm);

    const int tid   = threadIdx.x;
    const int lane  = tid & 31;
    const int wid   = tid >> 5;
    const int warpM = wid >> 1;
    const int warpN = wid & 1;
    const int bm    = blockIdx.x << 7;

    // load geometry: 128 rows x 12 uint4-chunks (16B) per matrix; 6/thread/matrix
    const int r0 = tid / 2;              // base row pattern: f = tid + l*256
    (void)r0;

    // ---- prologue: cp.async A (Gh/Gl rows bm..bm+127) and B tile 0 ----
#pragma unroll
    for (int l = 0; l < 6; l++) {
        int f = tid + (l << 8);
        int r = f / 12, u = f - r * 12;
        uint32_t so = (uint32_t)r * 192 + (swz((uint32_t)r, (uint32_t)u) << 4);
        cpa16(sbase + so,        g_Gh + (size_t)(bm + r) * 96 + (u << 3));
        cpa16(sbase + O_AL + so, g_Gl + (size_t)(bm + r) * 96 + (u << 3));
        cpa16(sbase + O_B + so,        g_Wfh + (size_t)r * 96 + (u << 3));
        cpa16(sbase + O_B + O_BL + so, g_Wfl + (size_t)r * 96 + (u << 3));
    }
    CPA_COMMIT();
    CPA_WAIT0();
    __syncthreads();

    const uint32_t a_row = (uint32_t)(warpM * 32 + (lane & 15));
    const uint32_t a_ck0 = (uint32_t)(lane >> 4);
    const uint32_t b_row = (uint32_t)(warpN * 64 + (lane & 7) + ((lane >> 4) << 3));
    const uint32_t b_ck0 = (uint32_t)((lane >> 3) & 1);

    for (int i = 0; i < 6; i++) {
        // prefetch B tile i+1 into the other buffer
        if (i + 1 < 6) {
            const int bnn = (i + 1) << 7;
            const uint32_t bo = O_B + (uint32_t)((i + 1) & 1) * O_BSZ;
#pragma unroll
            for (int l = 0; l < 6; l++) {
                int f = tid + (l << 8);
                int r = f / 12, u = f - r * 12;
                uint32_t so = (uint32_t)r * 192 + (swz((uint32_t)r, (uint32_t)u) << 4);
                cpa16(sbase + bo + so,        g_Wfh + (size_t)(bnn + r) * 96 + (u << 3));
                cpa16(sbase + bo + O_BL + so, g_Wfl + (size_t)(bnn + r) * 96 + (u << 3));
            }
            CPA_COMMIT();
        }

        // ---- compute tile i ----
        float acc[2][8][4];
#pragma unroll
        for (int a = 0; a < 2; a++)
#pragma unroll
            for (int j = 0; j < 8; j++)
#pragma unroll
                for (int q = 0; q < 4; q++) acc[a][j][q] = 0.0f;

        const uint32_t bbase = sbase + O_B + (uint32_t)(i & 1) * O_BSZ;
#pragma unroll
        for (int ks = 0; ks < 6; ks++) {
            uint32_t ah[2][4], al[2][4];
#pragma unroll
            for (int mt = 0; mt < 2; mt++) {
                uint32_t row = a_row + mt * 16;
                uint32_t addr = sbase + row * 192 + (swz(row, ks * 2 + a_ck0) << 4);
                ldsm4(ah[mt], addr);
                ldsm4(al[mt], addr + O_AL);
            }
            uint32_t bh2[4][4], bl2[4][4];
#pragma unroll
            for (int ng = 0; ng < 4; ng++) {
                uint32_t row = b_row + ng * 16;
                uint32_t addr = bbase + row * 192 + (swz(row, ks * 2 + b_ck0) << 4);
                ldsm4(bh2[ng], addr);
                ldsm4(bl2[ng], addr + O_BL);
            }
#pragma unroll
            for (int mt = 0; mt < 2; mt++)
#pragma unroll
                for (int nt = 0; nt < 8; nt++) {
                    const uint32_t* bh = &bh2[nt >> 1][(nt & 1) * 2];
                    const uint32_t* bl = &bl2[nt >> 1][(nt & 1) * 2];
                    mma16816(acc[mt][nt], ah[mt], bh);
                    mma16816(acc[mt][nt], ah[mt], bl);
                    mma16816(acc[mt][nt], al[mt], bh);
                }
        }

        // ---- epilogue tile i ----
#pragma unroll
        for (int mt = 0; mt < 2; mt++) {
            int m0 = bm + warpM * 32 + mt * 16 + (lane >> 2);
#pragma unroll
            for (int nt = 0; nt < 8; nt++) {
                int n = (i << 7) + warpN * 64 + nt * 8 + (lane & 3) * 2;
                float b0 = bout[n], b1 = bout[n + 1];
                *reinterpret_cast<float2*>(Y + (size_t)m0 * 768 + n) =
                    make_float2(acc[mt][nt][0] + b0, acc[mt][nt][1] + b1);
                *reinterpret_cast<float2*>(Y + (size_t)(m0 + 8) * 768 + n) =
                    make_float2(acc[mt][nt][2] + b0, acc[mt][nt][3] + b1);
            }
        }

        if (i + 1 < 6) CPA_WAIT0();
        __syncthreads();
    }
}

// ============================================================
extern "C" void kernel_launch(void* const* d_in, const int* in_sizes, int n_in,
                              void* d_out, int out_size)
{
    const float* x_rgb   = (const float*)d_in[0];
    const float* x_depth = (const float*)d_in[1];
    const float* W1      = (const float*)d_in[2];
    const float* b1      = (const float*)d_in[3];
    const float* W2      = (const float*)d_in[4];
    const float* b2      = (const float*)d_in[5];
    const float* Wout    = (const float*)d_in[6];
    const float* bout    = (const float*)d_in[7];
    const float* aw      = (const float*)d_in[8];

    float* out_rgb = (float*)d_out;
    float* out_fus = out_rgb + (size_t)M_TOK * K_IN;   // second half: x_fusion

    static bool attr_done = false;
    if (!attr_done) {
        cudaFuncSetAttribute(gemm_g,   cudaFuncAttributeMaxDynamicSharedMemorySize, 2 * GST);
        cudaFuncSetAttribute(gemm_out, cudaFuncAttributeMaxDynamicSharedMemorySize, O_SMEM);
        attr_done = true;
    }

    prep_kernel<<<288, 256>>>(W1, b1, W2, b2, Wout, aw);
    gemm_g<<<M_TOK / 128, 256, 2 * GST>>>(x_rgb, x_depth, out_rgb);
    gemm_out<<<M_TOK / 128, 256, O_SMEM>>>(bout, out_fus);
}

// round 8
// speedup vs baseline: 3.3484x; 1.2249x over previous
#include <cuda_runtime.h>
#include <cuda_bf16.h>
#include <math.h>
#include <stdint.h>

// Problem constants: B=8, N=4096, C=768, H=8, D=96
constexpr int M_TOK = 8 * 4096;   // 32768 tokens
constexpr int K_IN  = 768;        // C

// ---- device scratch (allocation-free rule: __device__ globals) ----
__device__ __align__(16) __nv_bfloat16 g_Wrh[96 * 768];  // hi(w1*sum_h Wv_rgb)
__device__ __align__(16) __nv_bfloat16 g_Wrl[96 * 768];  // lo
__device__ __align__(16) __nv_bfloat16 g_Wdh[96 * 768];  // hi(w0*sum_h Wv_depth)
__device__ __align__(16) __nv_bfloat16 g_Wdl[96 * 768];
__device__ __align__(16) __nv_bfloat16 g_Wfh[768 * 96];  // hi(sum_q Wout folded)
__device__ __align__(16) __nv_bfloat16 g_Wfl[768 * 96];
__device__ float g_bg[96];                                // combined bias for g

// ============================================================
// Helpers (plain sm_103-safe PTX: ldmatrix + mma.sync + cp.async)
// ============================================================
__device__ __forceinline__ uint32_t smem_u32(const void* p) {
    uint32_t a;
    asm("{ .reg .u64 t; cvta.to.shared.u64 t, %1; cvt.u32.u64 %0, t; }" : "=r"(a) : "l"(p));
    return a;
}
__device__ __forceinline__ void ldsm4(uint32_t* r, uint32_t addr) {
    asm volatile("ldmatrix.sync.aligned.m8n8.x4.shared.b16 {%0,%1,%2,%3}, [%4];"
                 : "=r"(r[0]), "=r"(r[1]), "=r"(r[2]), "=r"(r[3]) : "r"(addr));
}
__device__ __forceinline__ void mma16816(float* c, const uint32_t* a, const uint32_t* b) {
    asm volatile(
        "mma.sync.aligned.m16n8k16.row.col.f32.bf16.bf16.f32 "
        "{%0,%1,%2,%3}, {%4,%5,%6,%7}, {%8,%9}, {%0,%1,%2,%3};"
        : "+f"(c[0]), "+f"(c[1]), "+f"(c[2]), "+f"(c[3])
        : "r"(a[0]), "r"(a[1]), "r"(a[2]), "r"(a[3]), "r"(b[0]), "r"(b[1]));
}
__device__ __forceinline__ void cpa8(uint32_t d, const void* s) {
    asm volatile("cp.async.ca.shared.global [%0], [%1], 8;" :: "r"(d), "l"(s));
}
__device__ __forceinline__ void cpa16(uint32_t d, const void* s) {
    asm volatile("cp.async.cg.shared.global [%0], [%1], 16;" :: "r"(d), "l"(s));
}
#define CPA_COMMIT() asm volatile("cp.async.commit_group;" ::: "memory")
#define CPA_WAIT0()  asm volatile("cp.async.wait_group 0;" ::: "memory")

__device__ __forceinline__ uint32_t packbf2(__nv_bfloat16 a, __nv_bfloat16 b) {
    __nv_bfloat162 t; t.x = a; t.y = b;
    return *reinterpret_cast<uint32_t*>(&t);
}
__device__ __forceinline__ void splitbf(float v, __nv_bfloat16& h, __nv_bfloat16& l) {
    h = __float2bfloat16_rn(v);
    l = __float2bfloat16_rn(v - __bfloat162float(h));
}
// XOR swizzle on 16B chunks: conflict-free ldmatrix for 64B/192B rows
__device__ __forceinline__ uint32_t swz(uint32_t row, uint32_t chunk) {
    return chunk ^ ((row >> 1) & 3);
}

// ============================================================
// Prep: fold heads, sigmoid weights, split to bf16 hi/lo
// ============================================================
__global__ void prep_kernel(const float* __restrict__ W1, const float* __restrict__ b1,
                            const float* __restrict__ W2, const float* __restrict__ b2,
                            const float* __restrict__ Wout, const float* __restrict__ aw)
{
    int idx = blockIdx.x * blockDim.x + threadIdx.x;   // 0 .. 73727
    float w0 = 1.0f / (1.0f + expf(-aw[0]));
    float w1 = 1.0f / (1.0f + expf(-aw[1]));

    if (idx < 96 * 768) {
        int d = idx / 768;
        int c = idx - d * 768;
        float sr = 0.0f, sd = 0.0f;
#pragma unroll
        for (int h = 0; h < 8; h++) {
            sr += W1[(size_t)(1536 + h * 96 + d) * 768 + c];
            sd += W2[(size_t)(768  + h * 96 + d) * 768 + c];
        }
        __nv_bfloat16 h16, l16;
        splitbf(w1 * sr, h16, l16); g_Wrh[idx] = h16; g_Wrl[idx] = l16;
        splitbf(w0 * sd, h16, l16); g_Wdh[idx] = h16; g_Wdl[idx] = l16;
    }
    if (idx < 768 * 96) {
        int c = idx / 96;
        int d = idx - c * 96;
        float s = 0.0f;
#pragma unroll
        for (int q = 0; q < 8; q++) s += Wout[(size_t)c * 768 + q * 96 + d];
        __nv_bfloat16 h16, l16;
        splitbf(s, h16, l16); g_Wfh[idx] = h16; g_Wfl[idx] = l16;
    }
    if (idx < 96) {
        float sbr = 0.0f, sbd = 0.0f;
#pragma unroll
        for (int h = 0; h < 8; h++) {
            sbr += b1[1536 + h * 96 + idx];
            sbd += b2[768  + h * 96 + idx];
        }
        g_bg[idx] = w0 * sbd + w1 * sbr;
    }
}

// ============================================================
// FUSED kernel: per 128-row block,
//  Phase 1: G = Xr@Wr^T + Xd@Wd^T + bg  (K=1536, 48 stages of 32)
//           + fused x_rgb passthrough copy. G kept in SMEM (hi/lo).
//  Phase 2: Y = G @ Wf^T + bout  (K=96), 12 Wf tiles of 64 cols,
//           cp.async double-buffered.
// smem: phase1 pipeline 2x28672=57344 | phase2 G 49152 + B 2x24576 = 98304.
// 2 CTAs/SM -> all 256 CTAs resident (no wave quantization).
// ============================================================
constexpr uint32_t GST  = 28672;
constexpr uint32_t G_AL = 8192, G_BH = 16384, G_BL = 22528;
constexpr int G_STAGES  = 48;   // 1536 / 32

constexpr uint32_t P2_GL  = 24576;   // G lo offset (G hi at 0)
constexpr uint32_t P2_B   = 49152;   // B buffers start
constexpr uint32_t P2_BSZ = 24576;   // per B buffer (Bh 12K + Bl 12K)
constexpr uint32_t P2_BL  = 12288;   // Bl offset within a B buffer
constexpr int FUSED_SMEM  = 98304;

__global__ __launch_bounds__(256, 2) void fused_gemm(const float* __restrict__ Xr,
                                                     const float* __restrict__ Xd,
                                                     float* __restrict__ out_rgb,
                                                     const float* __restrict__ bout,
                                                     float* __restrict__ Y)
{
    extern __shared__ char dsm[];
    const uint32_t sbase = smem_u32(dsm);

    const int tid   = threadIdx.x;
    const int lane  = tid & 31;
    const int wid   = tid >> 5;
    const int warpM = wid >> 1;      // 0..3
    const int warpN = wid & 1;       // 0..1
    const int bm    = blockIdx.x << 7;

    // ======================= PHASE 1 =======================
    float acc[2][6][4];
#pragma unroll
    for (int i = 0; i < 2; i++)
#pragma unroll
        for (int j = 0; j < 6; j++)
#pragma unroll
            for (int q = 0; q < 4; q++) acc[i][j][q] = 0.0f;

    const int arow0 = tid >> 3;          // + 32*l  (A: 128 rows x 8 float4-cols)
    const int ac4   = tid & 7;
    const int brow0 = tid >> 3;          // + 32*l, l<3 (B: 96 rows x 8 uint2-cols)
    const int bu    = tid & 7;

    const uint32_t a_sts_sw = (swz((uint32_t)arow0, (uint32_t)(ac4 >> 1)) << 4) + (ac4 & 1) * 8;
    const uint32_t b_sts_sw = (swz((uint32_t)brow0, (uint32_t)(bu >> 1)) << 4) + (bu & 1) * 8;

    const uint32_t a_row = (uint32_t)(warpM * 32 + (lane & 15));
    const uint32_t a_ck0 = (uint32_t)(lane >> 4);
    const uint32_t b_row = (uint32_t)(warpN * 48 + (lane & 7) + ((lane >> 4) << 3));
    const uint32_t b_ck0 = (uint32_t)((lane >> 3) & 1);

    float4 av[4];

    // ---- prologue: stage 0 (rgb, kb = 0) ----
#pragma unroll
    for (int l = 0; l < 4; l++)
        av[l] = *reinterpret_cast<const float4*>(
            Xr + (size_t)(bm + arow0 + 32 * l) * 768 + (ac4 << 2));
#pragma unroll
    for (int l = 0; l < 3; l++) {
        uint32_t row = (uint32_t)(brow0 + 32 * l);
        cpa8(sbase + G_BH + row * 64 + b_sts_sw, g_Wrh + (size_t)row * 768 + (bu << 2));
        cpa8(sbase + G_BL + row * 64 + b_sts_sw, g_Wrl + (size_t)row * 768 + (bu << 2));
    }
    CPA_COMMIT();
    {
        char* st = dsm;
#pragma unroll
        for (int l = 0; l < 4; l++) {
            uint32_t ro = (uint32_t)(arow0 + 32 * l) * 64;
            __nv_bfloat16 h0, h1, h2, h3, l0, l1, l2, l3;
            splitbf(av[l].x, h0, l0); splitbf(av[l].y, h1, l1);
            splitbf(av[l].z, h2, l2); splitbf(av[l].w, h3, l3);
            *reinterpret_cast<uint2*>(st + ro + a_sts_sw) =
                make_uint2(packbf2(h0, h1), packbf2(h2, h3));
            *reinterpret_cast<uint2*>(st + G_AL + ro + a_sts_sw) =
                make_uint2(packbf2(l0, l1), packbf2(l2, l3));
            *reinterpret_cast<float4*>(
                out_rgb + (size_t)(bm + arow0 + 32 * l) * 768 + (ac4 << 2)) = av[l];
        }
    }
    CPA_WAIT0();
    __syncthreads();

    for (int s = 0; s < G_STAGES; s++) {
        const int sn = s + 1;
        if (sn < G_STAGES) {
            const float* X = (sn < 24) ? Xr : Xd;
            const __nv_bfloat16* BH = (sn < 24) ? g_Wrh : g_Wdh;
            const __nv_bfloat16* BL = (sn < 24) ? g_Wrl : g_Wdl;
            const int kb = ((sn < 24) ? sn : (sn - 24)) << 5;
            const uint32_t bo = (uint32_t)(sn & 1) * GST;
#pragma unroll
            for (int l = 0; l < 4; l++)
                av[l] = *reinterpret_cast<const float4*>(
                    X + (size_t)(bm + arow0 + 32 * l) * 768 + kb + (ac4 << 2));
#pragma unroll
            for (int l = 0; l < 3; l++) {
                uint32_t row = (uint32_t)(brow0 + 32 * l);
                size_t gi = (size_t)row * 768 + kb + (bu << 2);
                cpa8(sbase + bo + G_BH + row * 64 + b_sts_sw, BH + gi);
                cpa8(sbase + bo + G_BL + row * 64 + b_sts_sw, BL + gi);
            }
            CPA_COMMIT();
        }

        {
            const uint32_t sb = sbase + (uint32_t)(s & 1) * GST;
#pragma unroll
            for (int kk = 0; kk < 2; kk++) {
                uint32_t ah[2][4], al[2][4];
#pragma unroll
                for (int mt = 0; mt < 2; mt++) {
                    uint32_t row = a_row + mt * 16;
                    uint32_t addr = sb + row * 64 + (swz(row, kk * 2 + a_ck0) << 4);
                    ldsm4(ah[mt], addr);
                    ldsm4(al[mt], addr + G_AL);
                }
                uint32_t bh2[3][4], bl2[3][4];
#pragma unroll
                for (int ng = 0; ng < 3; ng++) {
                    uint32_t row = b_row + ng * 16;
                    uint32_t addr = sb + G_BH + row * 64 + (swz(row, kk * 2 + b_ck0) << 4);
                    ldsm4(bh2[ng], addr);
                    ldsm4(bl2[ng], addr + (G_BL - G_BH));
                }
#pragma unroll
                for (int mt = 0; mt < 2; mt++)
#pragma unroll
                    for (int nt = 0; nt < 6; nt++) {
                        const uint32_t* bh = &bh2[nt >> 1][(nt & 1) * 2];
                        const uint32_t* bl = &bl2[nt >> 1][(nt & 1) * 2];
                        mma16816(acc[mt][nt], ah[mt], bh);
                        mma16816(acc[mt][nt], ah[mt], bl);
                        mma16816(acc[mt][nt], al[mt], bh);
                    }
            }
        }

        if (sn < G_STAGES) {
            char* st = dsm + (sn & 1) * GST;
            const int kb = ((sn < 24) ? sn : (sn - 24)) << 5;
#pragma unroll
            for (int l = 0; l < 4; l++) {
                uint32_t ro = (uint32_t)(arow0 + 32 * l) * 64;
                __nv_bfloat16 h0, h1, h2, h3, l0, l1, l2, l3;
                splitbf(av[l].x, h0, l0); splitbf(av[l].y, h1, l1);
                splitbf(av[l].z, h2, l2); splitbf(av[l].w, h3, l3);
                *reinterpret_cast<uint2*>(st + ro + a_sts_sw) =
                    make_uint2(packbf2(h0, h1), packbf2(h2, h3));
                *reinterpret_cast<uint2*>(st + G_AL + ro + a_sts_sw) =
                    make_uint2(packbf2(l0, l1), packbf2(l2, l3));
            }
            if (sn < 24) {
#pragma unroll
                for (int l = 0; l < 4; l++)
                    *reinterpret_cast<float4*>(
                        out_rgb + (size_t)(bm + arow0 + 32 * l) * 768 + kb + (ac4 << 2)) = av[l];
            }
            CPA_WAIT0();
        }
        __syncthreads();
    }

    // ============== PHASE 1 -> 2 TRANSITION ==============
    // Prefetch B tile 0 (cols 0..63 of Wf) into B buffer 0.
#pragma unroll
    for (int l = 0; l < 3; l++) {
        int f = tid + (l << 8);
        int r = f / 12, u = f - r * 12;
        uint32_t so = (uint32_t)r * 192 + (swz((uint32_t)r, (uint32_t)u) << 4);
        cpa16(sbase + P2_B + so,         g_Wfh + (size_t)r * 96 + (u << 3));
        cpa16(sbase + P2_B + P2_BL + so, g_Wfl + (size_t)r * 96 + (u << 3));
    }
    CPA_COMMIT();

    // Write G block (hi/lo, bias added) into smem [0, 49152) with the
    // ldmatrix-A layout (rows of 192B, swizzled 16B chunks).
#pragma unroll
    for (int mt = 0; mt < 2; mt++) {
        uint32_t r0 = (uint32_t)(warpM * 32 + mt * 16 + (lane >> 2));
#pragma unroll
        for (int nt = 0; nt < 6; nt++) {
            int n = warpN * 48 + nt * 8 + (lane & 3) * 2;
            float b0 = g_bg[n], b1 = g_bg[n + 1];
            float v0 = acc[mt][nt][0] + b0, v1 = acc[mt][nt][1] + b1;
            float v2 = acc[mt][nt][2] + b0, v3 = acc[mt][nt][3] + b1;
            uint32_t u = (uint32_t)(warpN * 6 + nt);
            uint32_t off = (uint32_t)((lane & 3) << 2);
            uint32_t ad0 = r0 * 192 + (swz(r0, u) << 4) + off;
            uint32_t ad1 = (r0 + 8) * 192 + (swz(r0 + 8, u) << 4) + off;
            __nv_bfloat16 h0, l0, h1, l1;
            splitbf(v0, h0, l0); splitbf(v1, h1, l1);
            *reinterpret_cast<uint32_t*>(dsm + ad0)         = packbf2(h0, h1);
            *reinterpret_cast<uint32_t*>(dsm + P2_GL + ad0) = packbf2(l0, l1);
            splitbf(v2, h0, l0); splitbf(v3, h1, l1);
            *reinterpret_cast<uint32_t*>(dsm + ad1)         = packbf2(h0, h1);
            *reinterpret_cast<uint32_t*>(dsm + P2_GL + ad1) = packbf2(l0, l1);
        }
    }
    CPA_WAIT0();
    __syncthreads();

    // ======================= PHASE 2 =======================
    // Warp tile: 32 rows x 32 cols. 12 B tiles of 64 cols.
    const uint32_t p2b_row = (uint32_t)(warpN * 32 + (lane & 7) + ((lane >> 4) << 3));
    const uint32_t p2b_ck0 = (uint32_t)((lane >> 3) & 1);

    for (int i = 0; i < 12; i++) {
        if (i + 1 < 12) {
            const int cn = (i + 1) << 6;
            const uint32_t bo = P2_B + (uint32_t)((i + 1) & 1) * P2_BSZ;
#pragma unroll
            for (int l = 0; l < 3; l++) {
                int f = tid + (l << 8);
                int r = f / 12, u = f - r * 12;
                uint32_t so = (uint32_t)r * 192 + (swz((uint32_t)r, (uint32_t)u) << 4);
                cpa16(sbase + bo + so,         g_Wfh + (size_t)(cn + r) * 96 + (u << 3));
                cpa16(sbase + bo + P2_BL + so, g_Wfl + (size_t)(cn + r) * 96 + (u << 3));
            }
            CPA_COMMIT();
        }

        float acc2[2][4][4];
#pragma unroll
        for (int a = 0; a < 2; a++)
#pragma unroll
            for (int j = 0; j < 4; j++)
#pragma unroll
                for (int q = 0; q < 4; q++) acc2[a][j][q] = 0.0f;

        const uint32_t bbase = sbase + P2_B + (uint32_t)(i & 1) * P2_BSZ;
#pragma unroll
        for (int ks = 0; ks < 6; ks++) {
            uint32_t ah[2][4], al[2][4];
#pragma unroll
            for (int mt = 0; mt < 2; mt++) {
                uint32_t row = a_row + mt * 16;
                uint32_t addr = sbase + row * 192 + (swz(row, ks * 2 + a_ck0) << 4);
                ldsm4(ah[mt], addr);
                ldsm4(al[mt], addr + P2_GL);
            }
            uint32_t bh2[2][4], bl2[2][4];
#pragma unroll
            for (int ng = 0; ng < 2; ng++) {
                uint32_t row = p2b_row + ng * 16;
                uint32_t addr = bbase + row * 192 + (swz(row, ks * 2 + p2b_ck0) << 4);
                ldsm4(bh2[ng], addr);
                ldsm4(bl2[ng], addr + P2_BL);
            }
#pragma unroll
            for (int mt = 0; mt < 2; mt++)
#pragma unroll
                for (int nt = 0; nt < 4; nt++) {
                    const uint32_t* bh = &bh2[nt >> 1][(nt & 1) * 2];
                    const uint32_t* bl = &bl2[nt >> 1][(nt & 1) * 2];
                    mma16816(acc2[mt][nt], ah[mt], bh);
                    mma16816(acc2[mt][nt], ah[mt], bl);
                    mma16816(acc2[mt][nt], al[mt], bh);
                }
        }

        // epilogue tile i
#pragma unroll
        for (int mt = 0; mt < 2; mt++) {
            int m0 = bm + warpM * 32 + mt * 16 + (lane >> 2);
#pragma unroll
            for (int nt = 0; nt < 4; nt++) {
                int n = (i << 6) + warpN * 32 + nt * 8 + (lane & 3) * 2;
                float b0 = bout[n], b1 = bout[n + 1];
                *reinterpret_cast<float2*>(Y + (size_t)m0 * 768 + n) =
                    make_float2(acc2[mt][nt][0] + b0, acc2[mt][nt][1] + b1);
                *reinterpret_cast<float2*>(Y + (size_t)(m0 + 8) * 768 + n) =
                    make_float2(acc2[mt][nt][2] + b0, acc2[mt][nt][3] + b1);
            }
        }

        if (i + 1 < 12) CPA_WAIT0();
        __syncthreads();
    }
}

// ============================================================
extern "C" void kernel_launch(void* const* d_in, const int* in_sizes, int n_in,
                              void* d_out, int out_size)
{
    const float* x_rgb   = (const float*)d_in[0];
    const float* x_depth = (const float*)d_in[1];
    const float* W1      = (const float*)d_in[2];
    const float* b1      = (const float*)d_in[3];
    const float* W2      = (const float*)d_in[4];
    const float* b2      = (const float*)d_in[5];
    const float* Wout    = (const float*)d_in[6];
    const float* bout    = (const float*)d_in[7];
    const float* aw      = (const float*)d_in[8];

    float* out_rgb = (float*)d_out;
    float* out_fus = out_rgb + (size_t)M_TOK * K_IN;   // second half: x_fusion

    static bool attr_done = false;
    if (!attr_done) {
        cudaFuncSetAttribute(fused_gemm, cudaFuncAttributeMaxDynamicSharedMemorySize,
                             FUSED_SMEM);
        attr_done = true;
    }

    prep_kernel<<<288, 256>>>(W1, b1, W2, b2, Wout, aw);
    fused_gemm<<<M_TOK / 128, 256, FUSED_SMEM>>>(x_rgb, x_depth, out_rgb, bout, out_fus);
}

// round 9
// speedup vs baseline: 3.3945x; 1.0138x over previous
#include <cuda_runtime.h>
#include <cuda_bf16.h>
#include <math.h>
#include <stdint.h>

// Problem constants: B=8, N=4096, C=768, H=8, D=96
constexpr int M_TOK = 8 * 4096;   // 32768 tokens
constexpr int K_IN  = 768;        // C

// ---- device scratch (allocation-free rule: __device__ globals) ----
__device__ __align__(16) __nv_bfloat16 g_Wrh[96 * 768];  // hi(w1*sum_h Wv_rgb)
__device__ __align__(16) __nv_bfloat16 g_Wrl[96 * 768];  // lo
__device__ __align__(16) __nv_bfloat16 g_Wdh[96 * 768];  // hi(w0*sum_h Wv_depth)
__device__ __align__(16) __nv_bfloat16 g_Wdl[96 * 768];
__device__ __align__(16) __nv_bfloat16 g_Wfh[768 * 96];  // hi(sum_q Wout folded)
__device__ __align__(16) __nv_bfloat16 g_Wfl[768 * 96];
__device__ float g_bg[96];                                // combined bias for g

// ============================================================
// Helpers (plain sm_103-safe PTX: ldmatrix + mma.sync + cp.async)
// ============================================================
__device__ __forceinline__ uint32_t smem_u32(const void* p) {
    uint32_t a;
    asm("{ .reg .u64 t; cvta.to.shared.u64 t, %1; cvt.u32.u64 %0, t; }" : "=r"(a) : "l"(p));
    return a;
}
__device__ __forceinline__ void ldsm4(uint32_t* r, uint32_t addr) {
    asm volatile("ldmatrix.sync.aligned.m8n8.x4.shared.b16 {%0,%1,%2,%3}, [%4];"
                 : "=r"(r[0]), "=r"(r[1]), "=r"(r[2]), "=r"(r[3]) : "r"(addr));
}
// NOT volatile: register-only op, lets the compiler schedule freely.
__device__ __forceinline__ void mma16816(float* c, const uint32_t* a, const uint32_t* b) {
    asm("mma.sync.aligned.m16n8k16.row.col.f32.bf16.bf16.f32 "
        "{%0,%1,%2,%3}, {%4,%5,%6,%7}, {%8,%9}, {%0,%1,%2,%3};"
        : "+f"(c[0]), "+f"(c[1]), "+f"(c[2]), "+f"(c[3])
        : "r"(a[0]), "r"(a[1]), "r"(a[2]), "r"(a[3]), "r"(b[0]), "r"(b[1]));
}
__device__ __forceinline__ void cpa8(uint32_t d, const void* s) {
    asm volatile("cp.async.ca.shared.global [%0], [%1], 8;" :: "r"(d), "l"(s));
}
__device__ __forceinline__ void cpa16(uint32_t d, const void* s) {
    asm volatile("cp.async.cg.shared.global [%0], [%1], 16;" :: "r"(d), "l"(s));
}
#define CPA_COMMIT() asm volatile("cp.async.commit_group;" ::: "memory")
#define CPA_WAIT0()  asm volatile("cp.async.wait_group 0;" ::: "memory")

__device__ __forceinline__ uint32_t packbf2(__nv_bfloat16 a, __nv_bfloat16 b) {
    __nv_bfloat162 t; t.x = a; t.y = b;
    return *reinterpret_cast<uint32_t*>(&t);
}
__device__ __forceinline__ void splitbf(float v, __nv_bfloat16& h, __nv_bfloat16& l) {
    h = __float2bfloat16_rn(v);
    l = __float2bfloat16_rn(v - __bfloat162float(h));
}
// Fast RZ split of TWO floats -> (hi bf16x2, lo bf16x2).
// hi = truncated top 16 bits (PRMT pair), lo = exact residual, RN-packed.
__device__ __forceinline__ void split2(float x, float y, uint32_t& hi2, uint32_t& lo2) {
    uint32_t bx = __float_as_uint(x), by = __float_as_uint(y);
    hi2 = __byte_perm(bx, by, 0x7632);                 // {hi(x), hi(y)}
    float hx = __uint_as_float(bx & 0xFFFF0000u);
    float hy = __uint_as_float(by & 0xFFFF0000u);
    asm("cvt.rn.bf16x2.f32 %0, %1, %2;" : "=r"(lo2) : "f"(y - hy), "f"(x - hx));
}
// XOR swizzle on 16B chunks: conflict-free ldmatrix for 64B/192B rows
__device__ __forceinline__ uint32_t swz(uint32_t row, uint32_t chunk) {
    return chunk ^ ((row >> 1) & 3);
}

// ============================================================
// Prep: fold heads, sigmoid weights, split to bf16 hi/lo (RN, accurate)
// ============================================================
__global__ void prep_kernel(const float* __restrict__ W1, const float* __restrict__ b1,
                            const float* __restrict__ W2, const float* __restrict__ b2,
                            const float* __restrict__ Wout, const float* __restrict__ aw)
{
    int idx = blockIdx.x * blockDim.x + threadIdx.x;   // 0 .. 73727
    float w0 = 1.0f / (1.0f + expf(-aw[0]));
    float w1 = 1.0f / (1.0f + expf(-aw[1]));

    if (idx < 96 * 768) {
        int d = idx / 768;
        int c = idx - d * 768;
        float sr = 0.0f, sd = 0.0f;
#pragma unroll
        for (int h = 0; h < 8; h++) {
            sr += W1[(size_t)(1536 + h * 96 + d) * 768 + c];
            sd += W2[(size_t)(768  + h * 96 + d) * 768 + c];
        }
        __nv_bfloat16 h16, l16;
        splitbf(w1 * sr, h16, l16); g_Wrh[idx] = h16; g_Wrl[idx] = l16;
        splitbf(w0 * sd, h16, l16); g_Wdh[idx] = h16; g_Wdl[idx] = l16;
    }
    if (idx < 768 * 96) {
        int c = idx / 96;
        int d = idx - c * 96;
        float s = 0.0f;
#pragma unroll
        for (int q = 0; q < 8; q++) s += Wout[(size_t)c * 768 + q * 96 + d];
        __nv_bfloat16 h16, l16;
        splitbf(s, h16, l16); g_Wfh[idx] = h16; g_Wfl[idx] = l16;
    }
    if (idx < 96) {
        float sbr = 0.0f, sbd = 0.0f;
#pragma unroll
        for (int h = 0; h < 8; h++) {
            sbr += b1[1536 + h * 96 + idx];
            sbd += b2[768  + h * 96 + idx];
        }
        g_bg[idx] = w0 * sbd + w1 * sbr;
    }
}

// ============================================================
// FUSED kernel (see R7). This round: term-outer MMA ordering
// (acc reuse distance 1 -> 12) + fast RZ splits.
// ============================================================
constexpr uint32_t GST  = 28672;
constexpr uint32_t G_AL = 8192, G_BH = 16384, G_BL = 22528;
constexpr int G_STAGES  = 48;   // 1536 / 32

constexpr uint32_t P2_GL  = 24576;   // G lo offset (G hi at 0)
constexpr uint32_t P2_B   = 49152;   // B buffers start
constexpr uint32_t P2_BSZ = 24576;   // per B buffer (Bh 12K + Bl 12K)
constexpr uint32_t P2_BL  = 12288;   // Bl offset within a B buffer
constexpr int FUSED_SMEM  = 98304;

__global__ __launch_bounds__(256, 2) void fused_gemm(const float* __restrict__ Xr,
                                                     const float* __restrict__ Xd,
                                                     float* __restrict__ out_rgb,
                                                     const float* __restrict__ bout,
                                                     float* __restrict__ Y)
{
    extern __shared__ char dsm[];
    const uint32_t sbase = smem_u32(dsm);

    const int tid   = threadIdx.x;
    const int lane  = tid & 31;
    const int wid   = tid >> 5;
    const int warpM = wid >> 1;      // 0..3
    const int warpN = wid & 1;       // 0..1
    const int bm    = blockIdx.x << 7;

    // ======================= PHASE 1 =======================
    float acc[2][6][4];
#pragma unroll
    for (int i = 0; i < 2; i++)
#pragma unroll
        for (int j = 0; j < 6; j++)
#pragma unroll
            for (int q = 0; q < 4; q++) acc[i][j][q] = 0.0f;

    const int arow0 = tid >> 3;          // + 32*l  (A: 128 rows x 8 float4-cols)
    const int ac4   = tid & 7;
    const int brow0 = tid >> 3;          // + 32*l, l<3 (B: 96 rows x 8 uint2-cols)
    const int bu    = tid & 7;

    const uint32_t a_sts_sw = (swz((uint32_t)arow0, (uint32_t)(ac4 >> 1)) << 4) + (ac4 & 1) * 8;
    const uint32_t b_sts_sw = (swz((uint32_t)brow0, (uint32_t)(bu >> 1)) << 4) + (bu & 1) * 8;

    const uint32_t a_row = (uint32_t)(warpM * 32 + (lane & 15));
    const uint32_t a_ck0 = (uint32_t)(lane >> 4);
    const uint32_t b_row = (uint32_t)(warpN * 48 + (lane & 7) + ((lane >> 4) << 3));
    const uint32_t b_ck0 = (uint32_t)((lane >> 3) & 1);

    float4 av[4];

    // ---- prologue: stage 0 (rgb, kb = 0) ----
#pragma unroll
    for (int l = 0; l < 4; l++)
        av[l] = *reinterpret_cast<const float4*>(
            Xr + (size_t)(bm + arow0 + 32 * l) * 768 + (ac4 << 2));
#pragma unroll
    for (int l = 0; l < 3; l++) {
        uint32_t row = (uint32_t)(brow0 + 32 * l);
        cpa8(sbase + G_BH + row * 64 + b_sts_sw, g_Wrh + (size_t)row * 768 + (bu << 2));
        cpa8(sbase + G_BL + row * 64 + b_sts_sw, g_Wrl + (size_t)row * 768 + (bu << 2));
    }
    CPA_COMMIT();
    {
        char* st = dsm;
#pragma unroll
        for (int l = 0; l < 4; l++) {
            uint32_t ro = (uint32_t)(arow0 + 32 * l) * 64;
            uint32_t h01, l01, h23, l23;
            split2(av[l].x, av[l].y, h01, l01);
            split2(av[l].z, av[l].w, h23, l23);
            *reinterpret_cast<uint2*>(st + ro + a_sts_sw)        = make_uint2(h01, h23);
            *reinterpret_cast<uint2*>(st + G_AL + ro + a_sts_sw) = make_uint2(l01, l23);
            *reinterpret_cast<float4*>(
                out_rgb + (size_t)(bm + arow0 + 32 * l) * 768 + (ac4 << 2)) = av[l];
        }
    }
    CPA_WAIT0();
    __syncthreads();

    for (int s = 0; s < G_STAGES; s++) {
        const int sn = s + 1;
        if (sn < G_STAGES) {
            const float* X = (sn < 24) ? Xr : Xd;
            const __nv_bfloat16* BH = (sn < 24) ? g_Wrh : g_Wdh;
            const __nv_bfloat16* BL = (sn < 24) ? g_Wrl : g_Wdl;
            const int kb = ((sn < 24) ? sn : (sn - 24)) << 5;
            const uint32_t bo = (uint32_t)(sn & 1) * GST;
#pragma unroll
            for (int l = 0; l < 4; l++)
                av[l] = *reinterpret_cast<const float4*>(
                    X + (size_t)(bm + arow0 + 32 * l) * 768 + kb + (ac4 << 2));
#pragma unroll
            for (int l = 0; l < 3; l++) {
                uint32_t row = (uint32_t)(brow0 + 32 * l);
                size_t gi = (size_t)row * 768 + kb + (bu << 2);
                cpa8(sbase + bo + G_BH + row * 64 + b_sts_sw, BH + gi);
                cpa8(sbase + bo + G_BL + row * 64 + b_sts_sw, BL + gi);
            }
            CPA_COMMIT();
        }

        {
            const uint32_t sb = sbase + (uint32_t)(s & 1) * GST;
#pragma unroll
            for (int kk = 0; kk < 2; kk++) {
                uint32_t ah[2][4], al[2][4];
#pragma unroll
                for (int mt = 0; mt < 2; mt++) {
                    uint32_t row = a_row + mt * 16;
                    uint32_t addr = sb + row * 64 + (swz(row, kk * 2 + a_ck0) << 4);
                    ldsm4(ah[mt], addr);
                    ldsm4(al[mt], addr + G_AL);
                }
                uint32_t bh2[3][4], bl2[3][4];
#pragma unroll
                for (int ng = 0; ng < 3; ng++) {
                    uint32_t row = b_row + ng * 16;
                    uint32_t addr = sb + G_BH + row * 64 + (swz(row, kk * 2 + b_ck0) << 4);
                    ldsm4(bh2[ng], addr);
                    ldsm4(bl2[ng], addr + (G_BL - G_BH));
                }
                // term-outer: 12 independent accs between same-acc reuse
#pragma unroll
                for (int mt = 0; mt < 2; mt++)
#pragma unroll
                    for (int nt = 0; nt < 6; nt++)
                        mma16816(acc[mt][nt], ah[mt], &bh2[nt >> 1][(nt & 1) * 2]);
#pragma unroll
                for (int mt = 0; mt < 2; mt++)
#pragma unroll
                    for (int nt = 0; nt < 6; nt++)
                        mma16816(acc[mt][nt], ah[mt], &bl2[nt >> 1][(nt & 1) * 2]);
#pragma unroll
                for (int mt = 0; mt < 2; mt++)
#pragma unroll
                    for (int nt = 0; nt < 6; nt++)
                        mma16816(acc[mt][nt], al[mt], &bh2[nt >> 1][(nt & 1) * 2]);
            }
        }

        if (sn < G_STAGES) {
            char* st = dsm + (sn & 1) * GST;
            const int kb = ((sn < 24) ? sn : (sn - 24)) << 5;
#pragma unroll
            for (int l = 0; l < 4; l++) {
                uint32_t ro = (uint32_t)(arow0 + 32 * l) * 64;
                uint32_t h01, l01, h23, l23;
                split2(av[l].x, av[l].y, h01, l01);
                split2(av[l].z, av[l].w, h23, l23);
                *reinterpret_cast<uint2*>(st + ro + a_sts_sw)        = make_uint2(h01, h23);
                *reinterpret_cast<uint2*>(st + G_AL + ro + a_sts_sw) = make_uint2(l01, l23);
            }
            if (sn < 24) {
#pragma unroll
                for (int l = 0; l < 4; l++)
                    *reinterpret_cast<float4*>(
                        out_rgb + (size_t)(bm + arow0 + 32 * l) * 768 + kb + (ac4 << 2)) = av[l];
            }
            CPA_WAIT0();
        }
        __syncthreads();
    }

    // ============== PHASE 1 -> 2 TRANSITION ==============
#pragma unroll
    for (int l = 0; l < 3; l++) {
        int f = tid + (l << 8);
        int r = f / 12, u = f - r * 12;
        uint32_t so = (uint32_t)r * 192 + (swz((uint32_t)r, (uint32_t)u) << 4);
        cpa16(sbase + P2_B + so,         g_Wfh + (size_t)r * 96 + (u << 3));
        cpa16(sbase + P2_B + P2_BL + so, g_Wfl + (size_t)r * 96 + (u << 3));
    }
    CPA_COMMIT();

    // Write G block (hi/lo, bias added) into smem [0, 49152).
#pragma unroll
    for (int mt = 0; mt < 2; mt++) {
        uint32_t r0 = (uint32_t)(warpM * 32 + mt * 16 + (lane >> 2));
#pragma unroll
        for (int nt = 0; nt < 6; nt++) {
            int n = warpN * 48 + nt * 8 + (lane & 3) * 2;
            float b0 = g_bg[n], b1 = g_bg[n + 1];
            float v0 = acc[mt][nt][0] + b0, v1 = acc[mt][nt][1] + b1;
            float v2 = acc[mt][nt][2] + b0, v3 = acc[mt][nt][3] + b1;
            uint32_t u = (uint32_t)(warpN * 6 + nt);
            uint32_t off = (uint32_t)((lane & 3) << 2);
            uint32_t ad0 = r0 * 192 + (swz(r0, u) << 4) + off;
            uint32_t ad1 = (r0 + 8) * 192 + (swz(r0 + 8, u) << 4) + off;
            uint32_t h2, l2;
            split2(v0, v1, h2, l2);
            *reinterpret_cast<uint32_t*>(dsm + ad0)         = h2;
            *reinterpret_cast<uint32_t*>(dsm + P2_GL + ad0) = l2;
            split2(v2, v3, h2, l2);
            *reinterpret_cast<uint32_t*>(dsm + ad1)         = h2;
            *reinterpret_cast<uint32_t*>(dsm + P2_GL + ad1) = l2;
        }
    }
    CPA_WAIT0();
    __syncthreads();

    // ======================= PHASE 2 =======================
    const uint32_t p2b_row = (uint32_t)(warpN * 32 + (lane & 7) + ((lane >> 4) << 3));
    const uint32_t p2b_ck0 = (uint32_t)((lane >> 3) & 1);

    for (int i = 0; i < 12; i++) {
        if (i + 1 < 12) {
            const int cn = (i + 1) << 6;
            const uint32_t bo = P2_B + (uint32_t)((i + 1) & 1) * P2_BSZ;
#pragma unroll
            for (int l = 0; l < 3; l++) {
                int f = tid + (l << 8);
                int r = f / 12, u = f - r * 12;
                uint32_t so = (uint32_t)r * 192 + (swz((uint32_t)r, (uint32_t)u) << 4);
                cpa16(sbase + bo + so,         g_Wfh + (size_t)(cn + r) * 96 + (u << 3));
                cpa16(sbase + bo + P2_BL + so, g_Wfl + (size_t)(cn + r) * 96 + (u << 3));
            }
            CPA_COMMIT();
        }

        float acc2[2][4][4];
#pragma unroll
        for (int a = 0; a < 2; a++)
#pragma unroll
            for (int j = 0; j < 4; j++)
#pragma unroll
                for (int q = 0; q < 4; q++) acc2[a][j][q] = 0.0f;

        const uint32_t bbase = sbase + P2_B + (uint32_t)(i & 1) * P2_BSZ;
#pragma unroll
        for (int ks = 0; ks < 6; ks++) {
            uint32_t ah[2][4], al[2][4];
#pragma unroll
            for (int mt = 0; mt < 2; mt++) {
                uint32_t row = a_row + mt * 16;
                uint32_t addr = sbase + row * 192 + (swz(row, ks * 2 + a_ck0) << 4);
                ldsm4(ah[mt], addr);
                ldsm4(al[mt], addr + P2_GL);
            }
            uint32_t bh2[2][4], bl2[2][4];
#pragma unroll
            for (int ng = 0; ng < 2; ng++) {
                uint32_t row = p2b_row + ng * 16;
                uint32_t addr = bbase + row * 192 + (swz(row, ks * 2 + p2b_ck0) << 4);
                ldsm4(bh2[ng], addr);
                ldsm4(bl2[ng], addr + P2_BL);
            }
            // term-outer: 8 independent accs between same-acc reuse
#pragma unroll
            for (int mt = 0; mt < 2; mt++)
#pragma unroll
                for (int nt = 0; nt < 4; nt++)
                    mma16816(acc2[mt][nt], ah[mt], &bh2[nt >> 1][(nt & 1) * 2]);
#pragma unroll
            for (int mt = 0; mt < 2; mt++)
#pragma unroll
                for (int nt = 0; nt < 4; nt++)
                    mma16816(acc2[mt][nt], ah[mt], &bl2[nt >> 1][(nt & 1) * 2]);
#pragma unroll
            for (int mt = 0; mt < 2; mt++)
#pragma unroll
                for (int nt = 0; nt < 4; nt++)
                    mma16816(acc2[mt][nt], al[mt], &bh2[nt >> 1][(nt & 1) * 2]);
        }

        // epilogue tile i
#pragma unroll
        for (int mt = 0; mt < 2; mt++) {
            int m0 = bm + warpM * 32 + mt * 16 + (lane >> 2);
#pragma unroll
            for (int nt = 0; nt < 4; nt++) {
                int n = (i << 6) + warpN * 32 + nt * 8 + (lane & 3) * 2;
                float b0 = bout[n], b1 = bout[n + 1];
                *reinterpret_cast<float2*>(Y + (size_t)m0 * 768 + n) =
                    make_float2(acc2[mt][nt][0] + b0, acc2[mt][nt][1] + b1);
                *reinterpret_cast<float2*>(Y + (size_t)(m0 + 8) * 768 + n) =
                    make_float2(acc2[mt][nt][2] + b0, acc2[mt][nt][3] + b1);
            }
        }

        if (i + 1 < 12) CPA_WAIT0();
        __syncthreads();
    }
}

// ============================================================
extern "C" void kernel_launch(void* const* d_in, const int* in_sizes, int n_in,
                              void* d_out, int out_size)
{
    const float* x_rgb   = (const float*)d_in[0];
    const float* x_depth = (const float*)d_in[1];
    const float* W1      = (const float*)d_in[2];
    const float* b1      = (const float*)d_in[3];
    const float* W2      = (const float*)d_in[4];
    const float* b2      = (const float*)d_in[5];
    const float* Wout    = (const float*)d_in[6];
    const float* bout    = (const float*)d_in[7];
    const float* aw      = (const float*)d_in[8];

    float* out_rgb = (float*)d_out;
    float* out_fus = out_rgb + (size_t)M_TOK * K_IN;   // second half: x_fusion

    static bool attr_done = false;
    if (!attr_done) {
        cudaFuncSetAttribute(fused_gemm, cudaFuncAttributeMaxDynamicSharedMemorySize,
                             FUSED_SMEM);
        attr_done = true;
    }

    prep_kernel<<<288, 256>>>(W1, b1, W2, b2, Wout, aw);
    fused_gemm<<<M_TOK / 128, 256, FUSED_SMEM>>>(x_rgb, x_depth, out_rgb, bout, out_fus);
}